// round 7
// baseline (speedup 1.0000x reference)
#include <cuda_runtime.h>
#include <math.h>
#include <stdint.h>

#define NC 131071
#define NA 4095
#define NB 4095
#define TOTAL_NODES (NC + NA + NB)
#define HDIM 128
#define VOCAB 50000
#define VT 391                 // vocab tiles of 128 rows (391*128 = 50048)
#define TM 32

__device__ float g_h[(size_t)TOTAL_NODES * HDIM];
__device__ float g_c[(size_t)TOTAL_NODES * HDIM];
// T[v][0:128)=i, [128:256)=o, [256:384)=u, [384:512)=xf  (biases folded)
__device__ float g_T[(size_t)VOCAB * 512];
// tf32 hi/lo splits, plain row-major
__device__ uint32_t g_Ah[(size_t)VT * 128 * 128];
__device__ uint32_t g_Al[(size_t)VT * 128 * 128];
__device__ uint32_t g_Bh[128 * 512];
__device__ uint32_t g_Bl[128 * 512];

struct Seg { const int* feats; int gp0, gq0, M, ctaEnd; };

__device__ __forceinline__ float sigf(float x) { return 1.0f / (1.0f + expf(-x)); }
__device__ __forceinline__ uint32_t f2tf32(float v) {
    uint32_t r; asm("cvt.rna.tf32.f32 %0, %1;" : "=r"(r) : "f"(v)); return r;
}

// warp-level tf32 MMA, portable PTX (sm_80+): D[16x8] += A[16x8] * B[8x8]
__device__ __forceinline__ void mma8(float* c, const uint32_t* a, const uint32_t* b) {
    asm volatile(
        "mma.sync.aligned.m16n8k8.row.col.f32.tf32.tf32.f32 "
        "{%0,%1,%2,%3}, {%4,%5,%6,%7}, {%8,%9}, {%0,%1,%2,%3};"
        : "+f"(c[0]), "+f"(c[1]), "+f"(c[2]), "+f"(c[3])
        : "r"(a[0]), "r"(a[1]), "r"(a[2]), "r"(a[3]), "r"(b[0]), "r"(b[1]));
}

// ---------------------------------------------------------------------------
// Prep: tf32 hi/lo splits of emb and [W_iou | W_f], row-major.
// ---------------------------------------------------------------------------
__global__ void __launch_bounds__(256)
prepA_kernel(const float* __restrict__ emb)
{
    int idx = blockIdx.x * 256 + threadIdx.x;   // VT*128*128 total
    int v = idx >> 7;
    float a = (v < VOCAB) ? __ldg(&emb[idx]) : 0.f;
    uint32_t hb = f2tf32(a);
    g_Ah[idx] = hb;
    g_Al[idx] = f2tf32(a - __uint_as_float(hb));
}

__global__ void __launch_bounds__(256)
prepB_kernel(const float* __restrict__ Wiou, const float* __restrict__ Wf)
{
    int idx = blockIdx.x * 256 + threadIdx.x;   // 128*512 total
    int k = idx >> 9, n = idx & 511;
    float w = (n < 384) ? __ldg(&Wiou[(size_t)k * 384 + n])
                        : __ldg(&Wf[(size_t)k * 128 + (n - 384)]);
    uint32_t hb = f2tf32(w);
    g_Bh[idx] = hb;
    g_Bl[idx] = f2tf32(w - __uint_as_float(hb));
}

// ---------------------------------------------------------------------------
// Table GEMM via mma.sync tf32 (3x split): T = emb @ [W_iou|W_f] + bias.
// CTA: 128 rows x 64 cols; 8 warps as 4(m) x 2(n); warp tile 32x32 (2x4 mma tiles).
// smem u32 layout: Ah[128][132] | Al[128][132] | Bh[128][72] | Bl[128][72]
// ---------------------------------------------------------------------------
extern __shared__ uint32_t sh[];
__global__ void __launch_bounds__(256)
table_mma(const float* __restrict__ biou, const float* __restrict__ bf)
{
    const int tid = threadIdx.x, w = tid >> 5, lane = tid & 31;
    const int g = lane >> 2, tg = lane & 3;
    const int nBlk = blockIdx.y * 64;

    uint32_t* Ah = sh;                // 16896
    uint32_t* Al = sh + 16896;        // 16896
    uint32_t* Bh = sh + 33792;        // 9216
    uint32_t* Bl = sh + 43008;        // 9216

    // load A hi/lo (row stride 132 keeps 16B alignment: 132*4=528)
    const uint4* srcAh = (const uint4*)(g_Ah + (size_t)blockIdx.x * 16384);
    const uint4* srcAl = (const uint4*)(g_Al + (size_t)blockIdx.x * 16384);
    for (int i = tid; i < 4096; i += 256) {
        int r = i >> 5, q = i & 31;
        ((uint4*)(Ah + r * 132))[q] = srcAh[i];
        ((uint4*)(Al + r * 132))[q] = srcAl[i];
    }
    // load B hi/lo tile (row stride 72)
    for (int i = tid; i < 2048; i += 256) {
        int k = i >> 4, q = i & 15;
        ((uint4*)(Bh + k * 72))[q] = *(const uint4*)(g_Bh + k * 512 + nBlk + q * 4);
        ((uint4*)(Bl + k * 72))[q] = *(const uint4*)(g_Bl + k * 512 + nBlk + q * 4);
    }
    __syncthreads();

    const int wm = (w & 3) * 32;      // warp row base
    const int wn = (w >> 2) * 32;     // warp col base (within 64)

    float acc[2][4][4];
    #pragma unroll
    for (int mt = 0; mt < 2; mt++)
        #pragma unroll
        for (int nt = 0; nt < 4; nt++)
            #pragma unroll
            for (int e = 0; e < 4; e++) acc[mt][nt][e] = 0.f;

    #pragma unroll 2
    for (int k0 = 0; k0 < 128; k0 += 8) {
        uint32_t ah[2][4], al[2][4], bh[4][2], bl[4][2];
        #pragma unroll
        for (int mt = 0; mt < 2; mt++) {
            int r0 = wm + mt * 16 + g;
            int c0 = k0 + tg;
            ah[mt][0] = Ah[r0 * 132 + c0];
            ah[mt][1] = Ah[(r0 + 8) * 132 + c0];
            ah[mt][2] = Ah[r0 * 132 + c0 + 4];
            ah[mt][3] = Ah[(r0 + 8) * 132 + c0 + 4];
            al[mt][0] = Al[r0 * 132 + c0];
            al[mt][1] = Al[(r0 + 8) * 132 + c0];
            al[mt][2] = Al[r0 * 132 + c0 + 4];
            al[mt][3] = Al[(r0 + 8) * 132 + c0 + 4];
        }
        #pragma unroll
        for (int nt = 0; nt < 4; nt++) {
            int col = wn + nt * 8 + g;
            bh[nt][0] = Bh[(k0 + tg) * 72 + col];
            bh[nt][1] = Bh[(k0 + tg + 4) * 72 + col];
            bl[nt][0] = Bl[(k0 + tg) * 72 + col];
            bl[nt][1] = Bl[(k0 + tg + 4) * 72 + col];
        }
        #pragma unroll
        for (int mt = 0; mt < 2; mt++)
            #pragma unroll
            for (int nt = 0; nt < 4; nt++) {
                mma8(acc[mt][nt], ah[mt], bh[nt]);
                mma8(acc[mt][nt], al[mt], bh[nt]);
                mma8(acc[mt][nt], ah[mt], bl[nt]);
            }
    }

    // epilogue: c0:(row g, col 2tg) c1:(+1) c2:(row g+8) c3:(row g+8, col+1)
    #pragma unroll
    for (int mt = 0; mt < 2; mt++) {
        #pragma unroll
        for (int nt = 0; nt < 4; nt++) {
            int colg = nBlk + wn + nt * 8 + tg * 2;
            float bias0 = (colg < 384) ? __ldg(&biou[colg]) : __ldg(&bf[colg - 384]);
            float bias1 = (colg + 1 < 384) ? __ldg(&biou[colg + 1]) : __ldg(&bf[colg + 1 - 384]);
            int r0 = blockIdx.x * 128 + wm + mt * 16 + g;
            if (r0 < VOCAB) {
                g_T[(size_t)r0 * 512 + colg]     = acc[mt][nt][0] + bias0;
                g_T[(size_t)r0 * 512 + colg + 1] = acc[mt][nt][1] + bias1;
            }
            if (r0 + 8 < VOCAB) {
                g_T[(size_t)(r0 + 8) * 512 + colg]     = acc[mt][nt][2] + bias0;
                g_T[(size_t)(r0 + 8) * 512 + colg + 1] = acc[mt][nt][3] + bias1;
            }
        }
    }
}

// ---------------------------------------------------------------------------
// Leaf kernel: elementwise from T.
// ---------------------------------------------------------------------------
#define LEAVES_C 65536
#define LEAVES_AB 2048
__global__ void __launch_bounds__(256)
leaf_kernel(const int* __restrict__ cf, const int* __restrict__ af,
            const int* __restrict__ bfeat)
{
    int node = blockIdx.x * 2 + (threadIdx.x >> 7);
    int col = threadIdx.x & 127;
    int grow; const int* fp; int loc;
    if (node < LEAVES_C)                  { loc = node;                        grow = loc;           fp = cf; }
    else if (node < LEAVES_C + LEAVES_AB) { loc = node - LEAVES_C;             grow = NC + loc;      fp = af; }
    else                                  { loc = node - LEAVES_C - LEAVES_AB; grow = NC + NA + loc; fp = bfeat; }
    int f = __ldg(&fp[loc]);
    const float* T = g_T + (size_t)f * 512;
    float iv = sigf(__ldg(&T[col]));
    float ov = sigf(__ldg(&T[128 + col]));
    float uv = tanhf(__ldg(&T[256 + col]));
    float c = iv * uv;
    g_c[(size_t)grow * HDIM + col] = c;
    g_h[(size_t)grow * HDIM + col] = ov * tanhf(c);
}

// ---------------------------------------------------------------------------
// Internal level kernel (FFMA recurrent part), 2 CTAs/SM.
// ---------------------------------------------------------------------------
#define FMA4(acc, s, b) do { \
    (acc).x = fmaf((s), (b).x, (acc).x); (acc).y = fmaf((s), (b).y, (acc).y); \
    (acc).z = fmaf((s), (b).z, (acc).z); (acc).w = fmaf((s), (b).w, (acc).w); } while (0)

__global__ void __launch_bounds__(256, 2)
level_kernel(Seg s0, Seg s1, Seg s2,
             const float* __restrict__ Uiou, const float* __restrict__ Uf)
{
    __shared__ float Hp[2 * TM * HDIM];   // children h, 32KB

    int cta = blockIdx.x;
    Seg s; int rel;
    if (cta < s0.ctaEnd)      { s = s0; rel = cta; }
    else if (cta < s1.ctaEnd) { s = s1; rel = cta - s0.ctaEnd; }
    else                      { s = s2; rel = cta - s1.ctaEnd; }

    const int m0 = rel * TM;
    int Mrem = s.M - m0; if (Mrem > TM) Mrem = TM;
    const int tid = threadIdx.x;

    {
        const float4* gh4 = (const float4*)g_h;
        for (int i = tid; i < 2 * TM * 32; i += 256) {
            int r = i >> 5, q = i & 31;
            float4 v = make_float4(0.f, 0.f, 0.f, 0.f);
            if (r < 2 * Mrem)
                v = gh4[(size_t)(s.gq0 + 2 * m0 + r) * 32 + q];
            ((float4*)Hp)[i] = v;
        }
    }
    __syncthreads();

    const int ng = tid & 31;
    const int mb = (tid >> 5) * 4;

    float4 aI[4], aO[4], aU[4], aH0[4], aH1[4];
    #pragma unroll
    for (int mm = 0; mm < 4; mm++) {
        aI[mm] = make_float4(0, 0, 0, 0); aO[mm] = aI[mm]; aU[mm] = aI[mm];
        aH0[mm] = aI[mm]; aH1[mm] = aI[mm];
    }

    const float4* U4  = (const float4*)Uiou;
    const float4* Uf4 = (const float4*)Uf;

    #pragma unroll 2
    for (int k = 0; k < 128; k++) {
        const int r = k * 96 + ng;
        float4 ui = __ldg(&U4[r]);
        float4 uo = __ldg(&U4[r + 32]);
        float4 uu = __ldg(&U4[r + 64]);
        float4 uf = __ldg(&Uf4[k * 32 + ng]);
        #pragma unroll
        for (int mm = 0; mm < 4; mm++) {
            float h0 = Hp[(2 * (mb + mm)) * HDIM + k];
            float h1 = Hp[(2 * (mb + mm) + 1) * HDIM + k];
            float hs = h0 + h1;
            FMA4(aI[mm], hs, ui); FMA4(aO[mm], hs, uo); FMA4(aU[mm], hs, uu);
            FMA4(aH0[mm], h0, uf); FMA4(aH1[mm], h1, uf);
        }
    }

    #pragma unroll
    for (int mm = 0; mm < 4; mm++) {
        int mi = mb + mm;
        if (mi >= Mrem) continue;
        int gp = s.gp0 + m0 + mi;
        int f = __ldg(&s.feats[m0 + mi]);

        const float4* T4 = (const float4*)(g_T + (size_t)f * 512);
        float4 ti  = __ldg(&T4[ng]);
        float4 to  = __ldg(&T4[32 + ng]);
        float4 tu  = __ldg(&T4[64 + ng]);
        float4 txf = __ldg(&T4[96 + ng]);

        size_t cb = (size_t)(s.gq0 + 2 * (m0 + mi)) * 32 + ng;
        float4 c0v = ((const float4*)g_c)[cb];
        float4 c1v = ((const float4*)g_c)[cb + 32];

        const float *pI = (const float*)&aI[mm], *pO = (const float*)&aO[mm];
        const float *pU = (const float*)&aU[mm];
        const float *pH0 = (const float*)&aH0[mm], *pH1 = (const float*)&aH1[mm];
        const float *pti = (const float*)&ti, *pto = (const float*)&to;
        const float *ptu = (const float*)&tu, *pxf = (const float*)&txf;
        const float *pc0 = (const float*)&c0v, *pc1 = (const float*)&c1v;

        float4 cn, hn;
        float* pcn = (float*)&cn; float* phn = (float*)&hn;
        #pragma unroll
        for (int nn = 0; nn < 4; nn++) {
            float iv = sigf(pI[nn] + pti[nn]);
            float ov = sigf(pO[nn] + pto[nn]);
            float uv = tanhf(pU[nn] + ptu[nn]);
            float f0 = sigf(pxf[nn] + pH0[nn]);
            float f1 = sigf(pxf[nn] + pH1[nn]);
            float cv = iv * uv + f0 * pc0[nn] + f1 * pc1[nn];
            pcn[nn] = cv;
            phn[nn] = ov * tanhf(cv);
        }
        ((float4*)g_c)[(size_t)gp * 32 + ng] = cn;
        ((float4*)g_h)[(size_t)gp * 32 + ng] = hn;
    }
}

// ---------------------------------------------------------------------------
// Fusion head
// ---------------------------------------------------------------------------
__global__ void final_kernel(const float* __restrict__ fc1w, const float* __restrict__ fc1b,
                             const float* __restrict__ fc2w, const float* __restrict__ fc2b,
                             float* __restrict__ out)
{
    __shared__ float red[128]; __shared__ float hv[128]; __shared__ float y1[64];
    int t = threadIdx.x;
    const float* hC = g_h + (size_t)(NC - 1) * HDIM;
    const float* hA = g_h + (size_t)(NC + NA - 1) * HDIM;
    const float* hB = g_h + (size_t)(NC + NA + NB - 1) * HDIM;
    red[t] = hB[t] * hC[t];
    __syncthreads();
    for (int ss = 64; ss > 0; ss >>= 1) { if (t < ss) red[t] += red[t + ss]; __syncthreads(); }
    hv[t] = hA[t] * red[0];
    __syncthreads();
    if (t < 64) {
        float a = fc1b[t];
        #pragma unroll 4
        for (int i = 0; i < 128; i++) a = fmaf(hv[i], fc1w[i * 64 + t], a);
        y1[t] = fmaxf(a, 0.f);
    }
    __syncthreads();
    if (t < 3) {
        float a = fc2b[t];
        #pragma unroll
        for (int i = 0; i < 64; i++) a = fmaf(y1[i], fc2w[i * 3 + t], a);
        out[t] = fmaxf(a, 0.f);
    }
}

// ---------------------------------------------------------------------------
// Host side
// ---------------------------------------------------------------------------
static inline Seg make_seg(const int* feats, int base, int D, int it)
{
    int N = (1 << D) - 1;
    int d = D - 1 - it;
    Seg s;
    s.M = 1 << d;
    int pLoc = N - (1 << (d + 1)) + 1;
    int qLoc = N - (1 << (d + 2)) + 1;
    s.feats = feats + pLoc; s.gp0 = base + pLoc; s.gq0 = base + qLoc; s.ctaEnd = 0;
    return s;
}
static inline Seg empty_seg() { Seg s{nullptr, 0, 0, 0, 0}; return s; }

extern "C" void kernel_launch(void* const* d_in, const int* in_sizes, int n_in,
                              void* d_out, int out_size)
{
    const int*   cf    = (const int*)  d_in[0];
    const int*   af    = (const int*)  d_in[4];
    const int*   bfeat = (const int*)  d_in[8];
    const float* emb   = (const float*)d_in[12];
    const float* W_iou = (const float*)d_in[13];
    const float* b_iou = (const float*)d_in[14];
    const float* U_iou = (const float*)d_in[15];
    const float* W_f   = (const float*)d_in[16];
    const float* b_f   = (const float*)d_in[17];
    const float* U_f   = (const float*)d_in[18];
    const float* fc1w  = (const float*)d_in[19];
    const float* fc1b  = (const float*)d_in[20];
    const float* fc2w  = (const float*)d_in[21];
    const float* fc2b  = (const float*)d_in[22];

    // table smem: (16896*2 + 9216*2) u32 = 52224 u32 = 208896 B
    static int smem_set = 0;
    if (!smem_set) {
        cudaFuncSetAttribute(table_mma, cudaFuncAttributeMaxDynamicSharedMemorySize, 208896);
        smem_set = 1;
    }

    prepA_kernel<<<VT * 64, 256>>>(emb);
    prepB_kernel<<<256, 256>>>(W_iou, W_f);
    {
        dim3 grid(VT, 8);
        table_mma<<<grid, 256, 208896>>>(b_iou, b_f);
    }

    leaf_kernel<<<(LEAVES_C + 2 * LEAVES_AB) / 2, 256>>>(cf, af, bfeat);

    const int baseC = 0, baseA = NC, baseB = NC + NA;
    for (int it = 1; it < 17; it++) {
        Seg s0 = make_seg(cf, baseC, 17, it);
        Seg s1 = (it <= 11) ? make_seg(af, baseA, 12, it) : empty_seg();
        Seg s2 = (it <= 11) ? make_seg(bfeat, baseB, 12, it) : empty_seg();
        int e0 = (s0.M + TM - 1) / TM;
        int e1 = e0 + (s1.M > 0 ? (s1.M + TM - 1) / TM : 0);
        int e2 = e1 + (s2.M > 0 ? (s2.M + TM - 1) / TM : 0);
        s0.ctaEnd = e0; s1.ctaEnd = e1; s2.ctaEnd = e2;
        level_kernel<<<e2, 256>>>(s0, s1, s2, U_iou, U_f);
    }

    final_kernel<<<1, 128>>>(fc1w, fc1b, fc2w, fc2b, (float*)d_out);
}

// round 8
// speedup vs baseline: 1.1669x; 1.1669x over previous
#include <cuda_runtime.h>
#include <cuda_bf16.h>
#include <math.h>
#include <stdint.h>

#define NC 131071
#define NA 4095
#define NB 4095
#define TOTAL_NODES (NC + NA + NB)
#define HDIM 128
#define VOCAB 50000
#define VT 391                 // vocab tiles of 128 rows (391*128 = 50048)
#define TM 32

__device__ float g_h[(size_t)TOTAL_NODES * HDIM];
__device__ float g_c[(size_t)TOTAL_NODES * HDIM];
// T[v][0:128)=i, [128:256)=o, [256:384)=u, [384:512)=xf  (biases folded)
__device__ float g_T[(size_t)VOCAB * 512];
// bf16 hi/lo splits packed as u32 (2 bf16 along k).
// A: [VT*128 rows][64 u32]   B: [512 n][64 u32] (k-major per n => col layout for mma)
__device__ uint32_t g_Ah[(size_t)VT * 128 * 64];
__device__ uint32_t g_Al[(size_t)VT * 128 * 64];
__device__ uint32_t g_Bh[512 * 64];
__device__ uint32_t g_Bl[512 * 64];

struct Seg { const int* feats; int gp0, gq0, M, ctaEnd; };

__device__ __forceinline__ float sigf(float x) { return 1.0f / (1.0f + expf(-x)); }

// bf16 warp MMA (portable sm_80+): D[16x8] += A[16x16] * B[16x8]
__device__ __forceinline__ void mma16(float* c, const uint32_t* a, const uint32_t* b) {
    asm volatile(
        "mma.sync.aligned.m16n8k16.row.col.f32.bf16.bf16.f32 "
        "{%0,%1,%2,%3}, {%4,%5,%6,%7}, {%8,%9}, {%0,%1,%2,%3};"
        : "+f"(c[0]), "+f"(c[1]), "+f"(c[2]), "+f"(c[3])
        : "r"(a[0]), "r"(a[1]), "r"(a[2]), "r"(a[3]), "r"(b[0]), "r"(b[1]));
}

__device__ __forceinline__ uint32_t pack_bf16_hi(float x, float y) {
    __nv_bfloat162 v = __floats2bfloat162_rn(x, y);
    return *(uint32_t*)&v;
}

// ---------------------------------------------------------------------------
// Prep: bf16 hi/lo splits. A = emb (zero-padded to VT*128 rows),
// B = [W_iou | W_f] TRANSPOSED to [n][k].
// ---------------------------------------------------------------------------
__global__ void __launch_bounds__(256)
prepA_kernel(const float* __restrict__ emb)
{
    int idx = blockIdx.x * 256 + threadIdx.x;   // VT*128*64 total
    int v = idx >> 6, p = idx & 63;
    float x0 = 0.f, x1 = 0.f;
    if (v < VOCAB) {
        x0 = __ldg(&emb[(size_t)v * 128 + 2 * p]);
        x1 = __ldg(&emb[(size_t)v * 128 + 2 * p + 1]);
    }
    __nv_bfloat16 h0 = __float2bfloat16_rn(x0), h1 = __float2bfloat16_rn(x1);
    float l0 = x0 - __bfloat162float(h0), l1 = x1 - __bfloat162float(h1);
    uint32_t hp, lp;
    { __nv_bfloat162 t = {h0, h1}; hp = *(uint32_t*)&t; }
    lp = pack_bf16_hi(l0, l1);
    g_Ah[idx] = hp;
    g_Al[idx] = lp;
}

__global__ void __launch_bounds__(256)
prepB_kernel(const float* __restrict__ Wiou, const float* __restrict__ Wf)
{
    int idx = blockIdx.x * 256 + threadIdx.x;   // 512*64 total
    int n = idx >> 6, p = idx & 63;
    int k0 = 2 * p;
    float x0, x1;
    if (n < 384) {
        x0 = __ldg(&Wiou[(size_t)k0 * 384 + n]);
        x1 = __ldg(&Wiou[(size_t)(k0 + 1) * 384 + n]);
    } else {
        x0 = __ldg(&Wf[(size_t)k0 * 128 + (n - 384)]);
        x1 = __ldg(&Wf[(size_t)(k0 + 1) * 128 + (n - 384)]);
    }
    __nv_bfloat16 h0 = __float2bfloat16_rn(x0), h1 = __float2bfloat16_rn(x1);
    float l0 = x0 - __bfloat162float(h0), l1 = x1 - __bfloat162float(h1);
    uint32_t hp, lp;
    { __nv_bfloat162 t = {h0, h1}; hp = *(uint32_t*)&t; }
    lp = pack_bf16_hi(l0, l1);
    g_Bh[idx] = hp;
    g_Bl[idx] = lp;
}

// ---------------------------------------------------------------------------
// Table GEMM via bf16 mma.sync (3x split): T = emb @ [W_iou|W_f] + bias.
// CTA: 128 rows x 64 cols; 8 warps 4(m) x 2(n); warp tile 32x32.
// smem (u32, padded stride 68): Ah[128][68] | Al[128][68] | Bh[64][68] | Bl[64][68]
// = 26112 u32 = 104448 B  -> 2 CTAs/SM.
// ---------------------------------------------------------------------------
extern __shared__ uint32_t sh[];
__global__ void __launch_bounds__(256)
table_mma(const float* __restrict__ biou, const float* __restrict__ bf)
{
    const int tid = threadIdx.x, w = tid >> 5, lane = tid & 31;
    const int g = lane >> 2, tg = lane & 3;
    const int nBlk = blockIdx.y * 64;

    uint32_t* Ah = sh;                 // 128*68
    uint32_t* Al = sh + 8704;
    uint32_t* Bh = sh + 17408;         // 64*68
    uint32_t* Bl = sh + 21760;

    // A tiles (2048 uint4 per buffer), row = 16 uint4
    const uint4* srcAh = (const uint4*)(g_Ah + (size_t)blockIdx.x * 8192);
    const uint4* srcAl = (const uint4*)(g_Al + (size_t)blockIdx.x * 8192);
    for (int i = tid; i < 2048; i += 256) {
        int r = i >> 4, q = i & 15;
        *(uint4*)(Ah + r * 68 + q * 4) = srcAh[i];
        *(uint4*)(Al + r * 68 + q * 4) = srcAl[i];
    }
    // B tiles (1024 uint4 per buffer)
    for (int i = tid; i < 1024; i += 256) {
        int n = i >> 4, q = i & 15;
        *(uint4*)(Bh + n * 68 + q * 4) = *(const uint4*)(g_Bh + (size_t)(nBlk + n) * 64 + q * 4);
        *(uint4*)(Bl + n * 68 + q * 4) = *(const uint4*)(g_Bl + (size_t)(nBlk + n) * 64 + q * 4);
    }
    __syncthreads();

    const int wm = (w & 3) * 32;      // warp row base
    const int wn = (w >> 2) * 32;     // warp col base (within 64)

    float acc[2][4][4];
    #pragma unroll
    for (int mt = 0; mt < 2; mt++)
        #pragma unroll
        for (int nt = 0; nt < 4; nt++)
            #pragma unroll
            for (int e = 0; e < 4; e++) acc[mt][nt][e] = 0.f;

    #pragma unroll
    for (int ks = 0; ks < 8; ks++) {           // k-step of 16 -> 8 u32 pairs
        const int p0 = ks * 8;
        uint32_t ah[2][4], al[2][4], bh[4][2], bl[4][2];
        #pragma unroll
        for (int mt = 0; mt < 2; mt++) {
            int r0 = wm + mt * 16 + g;
            ah[mt][0] = Ah[r0 * 68 + p0 + tg];
            ah[mt][1] = Ah[(r0 + 8) * 68 + p0 + tg];
            ah[mt][2] = Ah[r0 * 68 + p0 + tg + 4];
            ah[mt][3] = Ah[(r0 + 8) * 68 + p0 + tg + 4];
            al[mt][0] = Al[r0 * 68 + p0 + tg];
            al[mt][1] = Al[(r0 + 8) * 68 + p0 + tg];
            al[mt][2] = Al[r0 * 68 + p0 + tg + 4];
            al[mt][3] = Al[(r0 + 8) * 68 + p0 + tg + 4];
        }
        #pragma unroll
        for (int nt = 0; nt < 4; nt++) {
            int col = wn + nt * 8 + g;
            bh[nt][0] = Bh[col * 68 + p0 + tg];
            bh[nt][1] = Bh[col * 68 + p0 + tg + 4];
            bl[nt][0] = Bl[col * 68 + p0 + tg];
            bl[nt][1] = Bl[col * 68 + p0 + tg + 4];
        }
        #pragma unroll
        for (int mt = 0; mt < 2; mt++)
            #pragma unroll
            for (int nt = 0; nt < 4; nt++) {
                mma16(acc[mt][nt], ah[mt], bh[nt]);
                mma16(acc[mt][nt], al[mt], bh[nt]);
                mma16(acc[mt][nt], ah[mt], bl[nt]);
            }
    }

    // epilogue: c0:(row g, col 2tg) c1:(col+1) c2:(row+8) c3:(row+8, col+1)
    #pragma unroll
    for (int mt = 0; mt < 2; mt++) {
        #pragma unroll
        for (int nt = 0; nt < 4; nt++) {
            int colg = nBlk + wn + nt * 8 + tg * 2;
            float bias0 = (colg < 384) ? __ldg(&biou[colg]) : __ldg(&bf[colg - 384]);
            float bias1 = (colg + 1 < 384) ? __ldg(&biou[colg + 1]) : __ldg(&bf[colg + 1 - 384]);
            int r0 = blockIdx.x * 128 + wm + mt * 16 + g;
            if (r0 < VOCAB) {
                g_T[(size_t)r0 * 512 + colg]     = acc[mt][nt][0] + bias0;
                g_T[(size_t)r0 * 512 + colg + 1] = acc[mt][nt][1] + bias1;
            }
            if (r0 + 8 < VOCAB) {
                g_T[(size_t)(r0 + 8) * 512 + colg]     = acc[mt][nt][2] + bias0;
                g_T[(size_t)(r0 + 8) * 512 + colg + 1] = acc[mt][nt][3] + bias1;
            }
        }
    }
}

// ---------------------------------------------------------------------------
// Leaf kernel: elementwise from T.
// ---------------------------------------------------------------------------
#define LEAVES_C 65536
#define LEAVES_AB 2048
__global__ void __launch_bounds__(256)
leaf_kernel(const int* __restrict__ cf, const int* __restrict__ af,
            const int* __restrict__ bfeat)
{
    int node = blockIdx.x * 2 + (threadIdx.x >> 7);
    int col = threadIdx.x & 127;
    int grow; const int* fp; int loc;
    if (node < LEAVES_C)                  { loc = node;                        grow = loc;           fp = cf; }
    else if (node < LEAVES_C + LEAVES_AB) { loc = node - LEAVES_C;             grow = NC + loc;      fp = af; }
    else                                  { loc = node - LEAVES_C - LEAVES_AB; grow = NC + NA + loc; fp = bfeat; }
    int f = __ldg(&fp[loc]);
    const float* T = g_T + (size_t)f * 512;
    float iv = sigf(__ldg(&T[col]));
    float ov = sigf(__ldg(&T[128 + col]));
    float uv = tanhf(__ldg(&T[256 + col]));
    float c = iv * uv;
    g_c[(size_t)grow * HDIM + col] = c;
    g_h[(size_t)grow * HDIM + col] = ov * tanhf(c);
}

// ---------------------------------------------------------------------------
// Internal level kernel (FFMA recurrent part), 2 CTAs/SM.
// ---------------------------------------------------------------------------
#define FMA4(acc, s, b) do { \
    (acc).x = fmaf((s), (b).x, (acc).x); (acc).y = fmaf((s), (b).y, (acc).y); \
    (acc).z = fmaf((s), (b).z, (acc).z); (acc).w = fmaf((s), (b).w, (acc).w); } while (0)

__global__ void __launch_bounds__(256, 2)
level_kernel(Seg s0, Seg s1, Seg s2,
             const float* __restrict__ Uiou, const float* __restrict__ Uf)
{
    __shared__ float Hp[2 * TM * HDIM];   // children h, 32KB

    int cta = blockIdx.x;
    Seg s; int rel;
    if (cta < s0.ctaEnd)      { s = s0; rel = cta; }
    else if (cta < s1.ctaEnd) { s = s1; rel = cta - s0.ctaEnd; }
    else                      { s = s2; rel = cta - s1.ctaEnd; }

    const int m0 = rel * TM;
    int Mrem = s.M - m0; if (Mrem > TM) Mrem = TM;
    const int tid = threadIdx.x;

    {
        const float4* gh4 = (const float4*)g_h;
        for (int i = tid; i < 2 * TM * 32; i += 256) {
            int r = i >> 5, q = i & 31;
            float4 v = make_float4(0.f, 0.f, 0.f, 0.f);
            if (r < 2 * Mrem)
                v = gh4[(size_t)(s.gq0 + 2 * m0 + r) * 32 + q];
            ((float4*)Hp)[i] = v;
        }
    }
    __syncthreads();

    const int ng = tid & 31;
    const int mb = (tid >> 5) * 4;

    float4 aI[4], aO[4], aU[4], aH0[4], aH1[4];
    #pragma unroll
    for (int mm = 0; mm < 4; mm++) {
        aI[mm] = make_float4(0, 0, 0, 0); aO[mm] = aI[mm]; aU[mm] = aI[mm];
        aH0[mm] = aI[mm]; aH1[mm] = aI[mm];
    }

    const float4* U4  = (const float4*)Uiou;
    const float4* Uf4 = (const float4*)Uf;

    #pragma unroll 2
    for (int k = 0; k < 128; k++) {
        const int r = k * 96 + ng;
        float4 ui = __ldg(&U4[r]);
        float4 uo = __ldg(&U4[r + 32]);
        float4 uu = __ldg(&U4[r + 64]);
        float4 uf = __ldg(&Uf4[k * 32 + ng]);
        #pragma unroll
        for (int mm = 0; mm < 4; mm++) {
            float h0 = Hp[(2 * (mb + mm)) * HDIM + k];
            float h1 = Hp[(2 * (mb + mm) + 1) * HDIM + k];
            float hs = h0 + h1;
            FMA4(aI[mm], hs, ui); FMA4(aO[mm], hs, uo); FMA4(aU[mm], hs, uu);
            FMA4(aH0[mm], h0, uf); FMA4(aH1[mm], h1, uf);
        }
    }

    #pragma unroll
    for (int mm = 0; mm < 4; mm++) {
        int mi = mb + mm;
        if (mi >= Mrem) continue;
        int gp = s.gp0 + m0 + mi;
        int f = __ldg(&s.feats[m0 + mi]);

        const float4* T4 = (const float4*)(g_T + (size_t)f * 512);
        float4 ti  = __ldg(&T4[ng]);
        float4 to  = __ldg(&T4[32 + ng]);
        float4 tu  = __ldg(&T4[64 + ng]);
        float4 txf = __ldg(&T4[96 + ng]);

        size_t cb = (size_t)(s.gq0 + 2 * (m0 + mi)) * 32 + ng;
        float4 c0v = ((const float4*)g_c)[cb];
        float4 c1v = ((const float4*)g_c)[cb + 32];

        const float *pI = (const float*)&aI[mm], *pO = (const float*)&aO[mm];
        const float *pU = (const float*)&aU[mm];
        const float *pH0 = (const float*)&aH0[mm], *pH1 = (const float*)&aH1[mm];
        const float *pti = (const float*)&ti, *pto = (const float*)&to;
        const float *ptu = (const float*)&tu, *pxf = (const float*)&txf;
        const float *pc0 = (const float*)&c0v, *pc1 = (const float*)&c1v;

        float4 cn, hn;
        float* pcn = (float*)&cn; float* phn = (float*)&hn;
        #pragma unroll
        for (int nn = 0; nn < 4; nn++) {
            float iv = sigf(pI[nn] + pti[nn]);
            float ov = sigf(pO[nn] + pto[nn]);
            float uv = tanhf(pU[nn] + ptu[nn]);
            float f0 = sigf(pxf[nn] + pH0[nn]);
            float f1 = sigf(pxf[nn] + pH1[nn]);
            float cv = iv * uv + f0 * pc0[nn] + f1 * pc1[nn];
            pcn[nn] = cv;
            phn[nn] = ov * tanhf(cv);
        }
        ((float4*)g_c)[(size_t)gp * 32 + ng] = cn;
        ((float4*)g_h)[(size_t)gp * 32 + ng] = hn;
    }
}

// ---------------------------------------------------------------------------
// Fusion head
// ---------------------------------------------------------------------------
__global__ void final_kernel(const float* __restrict__ fc1w, const float* __restrict__ fc1b,
                             const float* __restrict__ fc2w, const float* __restrict__ fc2b,
                             float* __restrict__ out)
{
    __shared__ float red[128]; __shared__ float hv[128]; __shared__ float y1[64];
    int t = threadIdx.x;
    const float* hC = g_h + (size_t)(NC - 1) * HDIM;
    const float* hA = g_h + (size_t)(NC + NA - 1) * HDIM;
    const float* hB = g_h + (size_t)(NC + NA + NB - 1) * HDIM;
    red[t] = hB[t] * hC[t];
    __syncthreads();
    for (int ss = 64; ss > 0; ss >>= 1) { if (t < ss) red[t] += red[t + ss]; __syncthreads(); }
    hv[t] = hA[t] * red[0];
    __syncthreads();
    if (t < 64) {
        float a = fc1b[t];
        #pragma unroll 4
        for (int i = 0; i < 128; i++) a = fmaf(hv[i], fc1w[i * 64 + t], a);
        y1[t] = fmaxf(a, 0.f);
    }
    __syncthreads();
    if (t < 3) {
        float a = fc2b[t];
        #pragma unroll
        for (int i = 0; i < 64; i++) a = fmaf(y1[i], fc2w[i * 3 + t], a);
        out[t] = fmaxf(a, 0.f);
    }
}

// ---------------------------------------------------------------------------
// Host side
// ---------------------------------------------------------------------------
static inline Seg make_seg(const int* feats, int base, int D, int it)
{
    int N = (1 << D) - 1;
    int d = D - 1 - it;
    Seg s;
    s.M = 1 << d;
    int pLoc = N - (1 << (d + 1)) + 1;
    int qLoc = N - (1 << (d + 2)) + 1;
    s.feats = feats + pLoc; s.gp0 = base + pLoc; s.gq0 = base + qLoc; s.ctaEnd = 0;
    return s;
}
static inline Seg empty_seg() { Seg s{nullptr, 0, 0, 0, 0}; return s; }

extern "C" void kernel_launch(void* const* d_in, const int* in_sizes, int n_in,
                              void* d_out, int out_size)
{
    const int*   cf    = (const int*)  d_in[0];
    const int*   af    = (const int*)  d_in[4];
    const int*   bfeat = (const int*)  d_in[8];
    const float* emb   = (const float*)d_in[12];
    const float* W_iou = (const float*)d_in[13];
    const float* b_iou = (const float*)d_in[14];
    const float* U_iou = (const float*)d_in[15];
    const float* W_f   = (const float*)d_in[16];
    const float* b_f   = (const float*)d_in[17];
    const float* U_f   = (const float*)d_in[18];
    const float* fc1w  = (const float*)d_in[19];
    const float* fc1b  = (const float*)d_in[20];
    const float* fc2w  = (const float*)d_in[21];
    const float* fc2b  = (const float*)d_in[22];

    // table smem: 26112 u32 = 104448 B
    cudaFuncSetAttribute(table_mma, cudaFuncAttributeMaxDynamicSharedMemorySize, 104448);

    prepA_kernel<<<VT * 32, 256>>>(emb);
    prepB_kernel<<<128, 256>>>(W_iou, W_f);
    {
        dim3 grid(VT, 8);
        table_mma<<<grid, 256, 104448>>>(b_iou, b_f);
    }

    leaf_kernel<<<(LEAVES_C + 2 * LEAVES_AB) / 2, 256>>>(cf, af, bfeat);

    const int baseC = 0, baseA = NC, baseB = NC + NA;
    for (int it = 1; it < 17; it++) {
        Seg s0 = make_seg(cf, baseC, 17, it);
        Seg s1 = (it <= 11) ? make_seg(af, baseA, 12, it) : empty_seg();
        Seg s2 = (it <= 11) ? make_seg(bfeat, baseB, 12, it) : empty_seg();
        int e0 = (s0.M + TM - 1) / TM;
        int e1 = e0 + (s1.M > 0 ? (s1.M + TM - 1) / TM : 0);
        int e2 = e1 + (s2.M > 0 ? (s2.M + TM - 1) / TM : 0);
        s0.ctaEnd = e0; s1.ctaEnd = e1; s2.ctaEnd = e2;
        level_kernel<<<e2, 256>>>(s0, s1, s2, U_iou, U_f);
    }

    final_kernel<<<1, 128>>>(fc1w, fc1b, fc2w, fc2b, (float*)d_out);
}

// round 12
// speedup vs baseline: 1.2144x; 1.0407x over previous
#include <cuda_runtime.h>
#include <cuda_bf16.h>
#include <math.h>
#include <stdint.h>

#define NC 131071
#define NA 4095
#define NB 4095
#define TOTAL_NODES (NC + NA + NB)
#define HDIM 128
#define VOCAB 50000
#define VT 391                 // vocab tiles of 128 rows (391*128 = 50048)
#define TM 32

__device__ float g_h[(size_t)TOTAL_NODES * HDIM];
__device__ float g_c[(size_t)TOTAL_NODES * HDIM];
// T[v][0:128)=i, [128:256)=o, [256:384)=u, [384:512)=xf  (biases folded)
__device__ float g_T[(size_t)VOCAB * 512];
// bf16 hi/lo splits packed as u32 (2 bf16 along k).
// A: [VT*128 rows][64 u32]   B: [512 n][64 u32] (k-major per n => col layout for mma)
__device__ uint32_t g_Ah[(size_t)VT * 128 * 64];
__device__ uint32_t g_Al[(size_t)VT * 128 * 64];
__device__ uint32_t g_Bh[512 * 64];
__device__ uint32_t g_Bl[512 * 64];

struct Seg { const int* feats; int gp0, gq0, M, ctaEnd; };

__device__ __forceinline__ float sigf(float x) { return 1.0f / (1.0f + expf(-x)); }

// bf16 warp MMA (portable sm_80+): D[16x8] += A[16x16] * B[16x8]
__device__ __forceinline__ void mma16(float* c, const uint32_t* a, const uint32_t* b) {
    asm volatile(
        "mma.sync.aligned.m16n8k16.row.col.f32.bf16.bf16.f32 "
        "{%0,%1,%2,%3}, {%4,%5,%6,%7}, {%8,%9}, {%0,%1,%2,%3};"
        : "+f"(c[0]), "+f"(c[1]), "+f"(c[2]), "+f"(c[3])
        : "r"(a[0]), "r"(a[1]), "r"(a[2]), "r"(a[3]), "r"(b[0]), "r"(b[1]));
}

__device__ __forceinline__ uint32_t pack_bf16_hi(float x, float y) {
    __nv_bfloat162 v = __floats2bfloat162_rn(x, y);
    return *(uint32_t*)&v;
}

// ---------------------------------------------------------------------------
// Prep: bf16 hi/lo splits. A = emb (zero-padded to VT*128 rows),
// B = [W_iou | W_f] TRANSPOSED to [n][k].
// ---------------------------------------------------------------------------
__global__ void __launch_bounds__(256)
prepA_kernel(const float* __restrict__ emb)
{
    int idx = blockIdx.x * 256 + threadIdx.x;   // VT*128*64 total
    int v = idx >> 6, p = idx & 63;
    float x0 = 0.f, x1 = 0.f;
    if (v < VOCAB) {
        x0 = __ldg(&emb[(size_t)v * 128 + 2 * p]);
        x1 = __ldg(&emb[(size_t)v * 128 + 2 * p + 1]);
    }
    __nv_bfloat16 h0 = __float2bfloat16_rn(x0), h1 = __float2bfloat16_rn(x1);
    float l0 = x0 - __bfloat162float(h0), l1 = x1 - __bfloat162float(h1);
    uint32_t hp, lp;
    { __nv_bfloat162 t = {h0, h1}; hp = *(uint32_t*)&t; }
    lp = pack_bf16_hi(l0, l1);
    g_Ah[idx] = hp;
    g_Al[idx] = lp;
}

__global__ void __launch_bounds__(256)
prepB_kernel(const float* __restrict__ Wiou, const float* __restrict__ Wf)
{
    int idx = blockIdx.x * 256 + threadIdx.x;   // 512*64 total
    int n = idx >> 6, p = idx & 63;
    int k0 = 2 * p;
    float x0, x1;
    if (n < 384) {
        x0 = __ldg(&Wiou[(size_t)k0 * 384 + n]);
        x1 = __ldg(&Wiou[(size_t)(k0 + 1) * 384 + n]);
    } else {
        x0 = __ldg(&Wf[(size_t)k0 * 128 + (n - 384)]);
        x1 = __ldg(&Wf[(size_t)(k0 + 1) * 128 + (n - 384)]);
    }
    __nv_bfloat16 h0 = __float2bfloat16_rn(x0), h1 = __float2bfloat16_rn(x1);
    float l0 = x0 - __bfloat162float(h0), l1 = x1 - __bfloat162float(h1);
    uint32_t hp, lp;
    { __nv_bfloat162 t = {h0, h1}; hp = *(uint32_t*)&t; }
    lp = pack_bf16_hi(l0, l1);
    g_Bh[idx] = hp;
    g_Bl[idx] = lp;
}

// ---------------------------------------------------------------------------
// Table GEMM via bf16 mma.sync (3x split): T = emb @ [W_iou|W_f] + bias.
// CTA: 128 rows x 64 cols; 8 warps 4(m) x 2(n); warp tile 32x32.
// smem (u32, padded stride 68): Ah[128][68] | Al[128][68] | Bh[64][68] | Bl[64][68]
// = 26112 u32 = 104448 B  -> 2 CTAs/SM.   (R8-proven, verbatim)
// ---------------------------------------------------------------------------
extern __shared__ uint32_t sh[];
__global__ void __launch_bounds__(256)
table_mma(const float* __restrict__ biou, const float* __restrict__ bf)
{
    const int tid = threadIdx.x, w = tid >> 5, lane = tid & 31;
    const int g = lane >> 2, tg = lane & 3;
    const int nBlk = blockIdx.y * 64;

    uint32_t* Ah = sh;                 // 128*68
    uint32_t* Al = sh + 8704;
    uint32_t* Bh = sh + 17408;         // 64*68
    uint32_t* Bl = sh + 21760;

    const uint4* srcAh = (const uint4*)(g_Ah + (size_t)blockIdx.x * 8192);
    const uint4* srcAl = (const uint4*)(g_Al + (size_t)blockIdx.x * 8192);
    for (int i = tid; i < 2048; i += 256) {
        int r = i >> 4, q = i & 15;
        *(uint4*)(Ah + r * 68 + q * 4) = srcAh[i];
        *(uint4*)(Al + r * 68 + q * 4) = srcAl[i];
    }
    for (int i = tid; i < 1024; i += 256) {
        int n = i >> 4, q = i & 15;
        *(uint4*)(Bh + n * 68 + q * 4) = *(const uint4*)(g_Bh + (size_t)(nBlk + n) * 64 + q * 4);
        *(uint4*)(Bl + n * 68 + q * 4) = *(const uint4*)(g_Bl + (size_t)(nBlk + n) * 64 + q * 4);
    }
    __syncthreads();

    const int wm = (w & 3) * 32;      // warp row base
    const int wn = (w >> 2) * 32;     // warp col base (within 64)

    float acc[2][4][4];
    #pragma unroll
    for (int mt = 0; mt < 2; mt++)
        #pragma unroll
        for (int nt = 0; nt < 4; nt++)
            #pragma unroll
            for (int e = 0; e < 4; e++) acc[mt][nt][e] = 0.f;

    #pragma unroll
    for (int ks = 0; ks < 8; ks++) {           // k-step of 16 -> 8 u32 pairs
        const int p0 = ks * 8;
        uint32_t ah[2][4], al[2][4], bh[4][2], bl[4][2];
        #pragma unroll
        for (int mt = 0; mt < 2; mt++) {
            int r0 = wm + mt * 16 + g;
            ah[mt][0] = Ah[r0 * 68 + p0 + tg];
            ah[mt][1] = Ah[(r0 + 8) * 68 + p0 + tg];
            ah[mt][2] = Ah[r0 * 68 + p0 + tg + 4];
            ah[mt][3] = Ah[(r0 + 8) * 68 + p0 + tg + 4];
            al[mt][0] = Al[r0 * 68 + p0 + tg];
            al[mt][1] = Al[(r0 + 8) * 68 + p0 + tg];
            al[mt][2] = Al[r0 * 68 + p0 + tg + 4];
            al[mt][3] = Al[(r0 + 8) * 68 + p0 + tg + 4];
        }
        #pragma unroll
        for (int nt = 0; nt < 4; nt++) {
            int col = wn + nt * 8 + g;
            bh[nt][0] = Bh[col * 68 + p0 + tg];
            bh[nt][1] = Bh[col * 68 + p0 + tg + 4];
            bl[nt][0] = Bl[col * 68 + p0 + tg];
            bl[nt][1] = Bl[col * 68 + p0 + tg + 4];
        }
        #pragma unroll
        for (int mt = 0; mt < 2; mt++)
            #pragma unroll
            for (int nt = 0; nt < 4; nt++) {
                mma16(acc[mt][nt], ah[mt], bh[nt]);
                mma16(acc[mt][nt], al[mt], bh[nt]);
                mma16(acc[mt][nt], ah[mt], bl[nt]);
            }
    }

    // epilogue: c0:(row g, col 2tg) c1:(col+1) c2:(row+8) c3:(row+8, col+1)
    #pragma unroll
    for (int mt = 0; mt < 2; mt++) {
        #pragma unroll
        for (int nt = 0; nt < 4; nt++) {
            int colg = nBlk + wn + nt * 8 + tg * 2;
            float bias0 = (colg < 384) ? __ldg(&biou[colg]) : __ldg(&bf[colg - 384]);
            float bias1 = (colg + 1 < 384) ? __ldg(&biou[colg + 1]) : __ldg(&bf[colg + 1 - 384]);
            int r0 = blockIdx.x * 128 + wm + mt * 16 + g;
            if (r0 < VOCAB) {
                g_T[(size_t)r0 * 512 + colg]     = acc[mt][nt][0] + bias0;
                g_T[(size_t)r0 * 512 + colg + 1] = acc[mt][nt][1] + bias1;
            }
            if (r0 + 8 < VOCAB) {
                g_T[(size_t)(r0 + 8) * 512 + colg]     = acc[mt][nt][2] + bias0;
                g_T[(size_t)(r0 + 8) * 512 + colg + 1] = acc[mt][nt][3] + bias1;
            }
        }
    }
}

// ---------------------------------------------------------------------------
// Leaf kernel (R8-proven, verbatim): elementwise from T.
// ---------------------------------------------------------------------------
#define LEAVES_C 65536
#define LEAVES_AB 2048
__global__ void __launch_bounds__(256)
leaf_kernel(const int* __restrict__ cf, const int* __restrict__ af,
            const int* __restrict__ bfeat)
{
    int node = blockIdx.x * 2 + (threadIdx.x >> 7);
    int col = threadIdx.x & 127;
    int grow; const int* fp; int loc;
    if (node < LEAVES_C)                  { loc = node;                        grow = loc;           fp = cf; }
    else if (node < LEAVES_C + LEAVES_AB) { loc = node - LEAVES_C;             grow = NC + loc;      fp = af; }
    else                                  { loc = node - LEAVES_C - LEAVES_AB; grow = NC + NA + loc; fp = bfeat; }
    int f = __ldg(&fp[loc]);
    const float* T = g_T + (size_t)f * 512;
    float iv = sigf(__ldg(&T[col]));
    float ov = sigf(__ldg(&T[128 + col]));
    float uv = tanhf(__ldg(&T[256 + col]));
    float c = iv * uv;
    g_c[(size_t)grow * HDIM + col] = c;
    g_h[(size_t)grow * HDIM + col] = ov * tanhf(c);
}

// ---------------------------------------------------------------------------
// FFMA level kernel — R4-MEASURED variant, verbatim (48KB smem incl. Hs,
// software prefetch of U rows, no min-CTAs clause; it=2 launch = 160us).
// ---------------------------------------------------------------------------
#define FMA4(acc, s, b) do { \
    (acc).x = fmaf((s), (b).x, (acc).x); (acc).y = fmaf((s), (b).y, (acc).y); \
    (acc).z = fmaf((s), (b).z, (acc).z); (acc).w = fmaf((s), (b).w, (acc).w); } while (0)

__global__ void __launch_bounds__(256)
level_kernel(Seg s0, Seg s1, Seg s2,
             const float* __restrict__ Uiou, const float* __restrict__ Uf)
{
    __shared__ float Hp[2 * TM * HDIM];   // children h, 32KB
    __shared__ float Hs[TM * HDIM];       // h0+h1,      16KB

    int cta = blockIdx.x;
    Seg s; int rel;
    if (cta < s0.ctaEnd)      { s = s0; rel = cta; }
    else if (cta < s1.ctaEnd) { s = s1; rel = cta - s0.ctaEnd; }
    else                      { s = s2; rel = cta - s1.ctaEnd; }

    const int m0 = rel * TM;
    int Mrem = s.M - m0; if (Mrem > TM) Mrem = TM;
    const int tid = threadIdx.x;

    {
        const float4* gh4 = (const float4*)g_h;
        for (int i = tid; i < 2 * TM * 32; i += 256) {
            int r = i >> 5, q = i & 31;
            float4 v = make_float4(0.f, 0.f, 0.f, 0.f);
            if (r < 2 * Mrem)
                v = gh4[(size_t)(s.gq0 + 2 * m0 + r) * 32 + q];
            ((float4*)Hp)[i] = v;
        }
    }
    __syncthreads();
    for (int i = tid; i < TM * 32; i += 256) {
        int m = i >> 5, q = i & 31;
        float4 a = ((const float4*)Hp)[(2 * m) * 32 + q];
        float4 b = ((const float4*)Hp)[(2 * m + 1) * 32 + q];
        ((float4*)Hs)[i] = make_float4(a.x + b.x, a.y + b.y, a.z + b.z, a.w + b.w);
    }
    __syncthreads();

    const int ng = tid & 31;
    const int mb = (tid >> 5) * 4;

    float4 aI[4], aO[4], aU[4], aH0[4], aH1[4];
    #pragma unroll
    for (int mm = 0; mm < 4; mm++) {
        aI[mm] = make_float4(0,0,0,0); aO[mm] = aI[mm]; aU[mm] = aI[mm];
        aH0[mm] = aI[mm]; aH1[mm] = aI[mm];
    }

    const float4* U4  = (const float4*)Uiou;   // row k: 96 float4
    const float4* Uf4 = (const float4*)Uf;     // row k: 32 float4

    float4 ui = __ldg(&U4[ng]);
    float4 uo = __ldg(&U4[ng + 32]);
    float4 uu = __ldg(&U4[ng + 64]);
    float4 uf = __ldg(&Uf4[ng]);

    #pragma unroll 2
    for (int k = 0; k < 127; k++) {
        const int r = (k + 1) * 96 + ng;
        float4 nui = __ldg(&U4[r]);
        float4 nuo = __ldg(&U4[r + 32]);
        float4 nuu = __ldg(&U4[r + 64]);
        float4 nuf = __ldg(&Uf4[(k + 1) * 32 + ng]);
        #pragma unroll
        for (int mm = 0; mm < 4; mm++) {
            float hs = Hs[(mb + mm) * HDIM + k];
            float h0 = Hp[(2 * (mb + mm)) * HDIM + k];
            float h1 = Hp[(2 * (mb + mm) + 1) * HDIM + k];
            FMA4(aI[mm], hs, ui); FMA4(aO[mm], hs, uo); FMA4(aU[mm], hs, uu);
            FMA4(aH0[mm], h0, uf); FMA4(aH1[mm], h1, uf);
        }
        ui = nui; uo = nuo; uu = nuu; uf = nuf;
    }
    {
        const int k = 127;
        #pragma unroll
        for (int mm = 0; mm < 4; mm++) {
            float hs = Hs[(mb + mm) * HDIM + k];
            float h0 = Hp[(2 * (mb + mm)) * HDIM + k];
            float h1 = Hp[(2 * (mb + mm) + 1) * HDIM + k];
            FMA4(aI[mm], hs, ui); FMA4(aO[mm], hs, uo); FMA4(aU[mm], hs, uu);
            FMA4(aH0[mm], h0, uf); FMA4(aH1[mm], h1, uf);
        }
    }

    #pragma unroll
    for (int mm = 0; mm < 4; mm++) {
        int mi = mb + mm;
        if (mi >= Mrem) continue;
        int gp = s.gp0 + m0 + mi;
        int f = __ldg(&s.feats[m0 + mi]);

        const float4* T4 = (const float4*)(g_T + (size_t)f * 512);
        float4 ti  = __ldg(&T4[ng]);
        float4 to  = __ldg(&T4[32 + ng]);
        float4 tu  = __ldg(&T4[64 + ng]);
        float4 txf = __ldg(&T4[96 + ng]);

        size_t cb = (size_t)(s.gq0 + 2 * (m0 + mi)) * 32 + ng;
        float4 c0v = ((const float4*)g_c)[cb];
        float4 c1v = ((const float4*)g_c)[cb + 32];

        const float *pI = (const float*)&aI[mm], *pO = (const float*)&aO[mm];
        const float *pU = (const float*)&aU[mm];
        const float *pH0 = (const float*)&aH0[mm], *pH1 = (const float*)&aH1[mm];
        const float *pti = (const float*)&ti, *pto = (const float*)&to;
        const float *ptu = (const float*)&tu, *pxf = (const float*)&txf;
        const float *pc0 = (const float*)&c0v, *pc1 = (const float*)&c1v;

        float4 cn, hn;
        float* pcn = (float*)&cn; float* phn = (float*)&hn;
        #pragma unroll
        for (int nn = 0; nn < 4; nn++) {
            float iv = sigf(pI[nn] + pti[nn]);
            float ov = sigf(pO[nn] + pto[nn]);
            float uv = tanhf(pU[nn] + ptu[nn]);
            float f0 = sigf(pxf[nn] + pH0[nn]);
            float f1 = sigf(pxf[nn] + pH1[nn]);
            float cv = iv * uv + f0 * pc0[nn] + f1 * pc1[nn];
            pcn[nn] = cv;
            phn[nn] = ov * tanhf(cv);
        }
        ((float4*)g_c)[(size_t)gp * 32 + ng] = cn;
        ((float4*)g_h)[(size_t)gp * 32 + ng] = hn;
    }
}

// ---------------------------------------------------------------------------
// Fusion head
// ---------------------------------------------------------------------------
__global__ void final_kernel(const float* __restrict__ fc1w, const float* __restrict__ fc1b,
                             const float* __restrict__ fc2w, const float* __restrict__ fc2b,
                             float* __restrict__ out)
{
    __shared__ float red[128]; __shared__ float hv[128]; __shared__ float y1[64];
    int t = threadIdx.x;
    const float* hC = g_h + (size_t)(NC - 1) * HDIM;
    const float* hA = g_h + (size_t)(NC + NA - 1) * HDIM;
    const float* hB = g_h + (size_t)(NC + NA + NB - 1) * HDIM;
    red[t] = hB[t] * hC[t];
    __syncthreads();
    for (int ss = 64; ss > 0; ss >>= 1) { if (t < ss) red[t] += red[t + ss]; __syncthreads(); }
    hv[t] = hA[t] * red[0];
    __syncthreads();
    if (t < 64) {
        float a = fc1b[t];
        #pragma unroll 4
        for (int i = 0; i < 128; i++) a = fmaf(hv[i], fc1w[i * 64 + t], a);
        y1[t] = fmaxf(a, 0.f);
    }
    __syncthreads();
    if (t < 3) {
        float a = fc2b[t];
        #pragma unroll
        for (int i = 0; i < 64; i++) a = fmaf(y1[i], fc2w[i * 3 + t], a);
        out[t] = fmaxf(a, 0.f);
    }
}

// ---------------------------------------------------------------------------
// Host side
// ---------------------------------------------------------------------------
static inline Seg make_seg(const int* feats, int base, int D, int it)
{
    int N = (1 << D) - 1;
    int d = D - 1 - it;
    Seg s;
    s.M = 1 << d;
    int pLoc = N - (1 << (d + 1)) + 1;
    int qLoc = N - (1 << (d + 2)) + 1;
    s.feats = feats + pLoc; s.gp0 = base + pLoc; s.gq0 = base + qLoc; s.ctaEnd = 0;
    return s;
}
static inline Seg empty_seg() { Seg s{nullptr, 0, 0, 0, 0}; return s; }

extern "C" void kernel_launch(void* const* d_in, const int* in_sizes, int n_in,
                              void* d_out, int out_size)
{
    const int*   cf    = (const int*)  d_in[0];
    const int*   af    = (const int*)  d_in[4];
    const int*   bfeat = (const int*)  d_in[8];
    const float* emb   = (const float*)d_in[12];
    const float* W_iou = (const float*)d_in[13];
    const float* b_iou = (const float*)d_in[14];
    const float* U_iou = (const float*)d_in[15];
    const float* W_f   = (const float*)d_in[16];
    const float* b_f   = (const float*)d_in[17];
    const float* U_f   = (const float*)d_in[18];
    const float* fc1w  = (const float*)d_in[19];
    const float* fc1b  = (const float*)d_in[20];
    const float* fc2w  = (const float*)d_in[21];
    const float* fc2b  = (const float*)d_in[22];

    // table smem: 26112 u32 = 104448 B
    cudaFuncSetAttribute(table_mma, cudaFuncAttributeMaxDynamicSharedMemorySize, 104448);

    prepA_kernel<<<VT * 32, 256>>>(emb);
    prepB_kernel<<<128, 256>>>(W_iou, W_f);
    {
        dim3 grid(VT, 8);
        table_mma<<<grid, 256, 104448>>>(b_iou, b_f);
    }

    leaf_kernel<<<(LEAVES_C + 2 * LEAVES_AB) / 2, 256>>>(cf, af, bfeat);

    const int baseC = 0, baseA = NC, baseB = NC + NA;
    for (int it = 1; it < 17; it++) {
        Seg s0 = make_seg(cf, baseC, 17, it);
        Seg s1 = (it <= 11) ? make_seg(af, baseA, 12, it) : empty_seg();
        Seg s2 = (it <= 11) ? make_seg(bfeat, baseB, 12, it) : empty_seg();
        int e0 = (s0.M + TM - 1) / TM;
        int e1 = e0 + (s1.M > 0 ? (s1.M + TM - 1) / TM : 0);
        int e2 = e1 + (s2.M > 0 ? (s2.M + TM - 1) / TM : 0);
        s0.ctaEnd = e0; s1.ctaEnd = e1; s2.ctaEnd = e2;
        level_kernel<<<e2, 256>>>(s0, s1, s2, U_iou, U_f);
    }

    final_kernel<<<1, 128>>>(fc1w, fc1b, fc2w, fc2b, (float*)d_out);
}

// round 14
// speedup vs baseline: 1.2330x; 1.0153x over previous
#include <cuda_runtime.h>
#include <cuda_bf16.h>
#include <math.h>
#include <stdint.h>

#define NC 131071
#define NA 4095
#define NB 4095
#define TOTAL_NODES (NC + NA + NB)
#define HDIM 128
#define VOCAB 50000
#define VT 391                 // vocab tiles of 128 rows (391*128 = 50048)
#define TM 32

__device__ float g_h[(size_t)TOTAL_NODES * HDIM];
__device__ float g_c[(size_t)TOTAL_NODES * HDIM];
// T[v][0:128)=i, [128:256)=o, [256:384)=u, [384:512)=xf  (biases folded)
__device__ float g_T[(size_t)VOCAB * 512];
// bf16 hi/lo splits packed as u32 (2 bf16 along k).
__device__ uint32_t g_Ah[(size_t)VT * 128 * 64];   // emb rows
__device__ uint32_t g_Al[(size_t)VT * 128 * 64];
__device__ uint32_t g_Bh[512 * 64];                // [W_iou|W_f] transposed [n][k]
__device__ uint32_t g_Bl[512 * 64];
__device__ uint32_t g_UH[512 * 64];                // [U_iou|U_f] transposed [n][k]
__device__ uint32_t g_UL[512 * 64];
// scratch for mma levels
__device__ float g_Y1[(size_t)32768 * 384];        // iou pre-activations
__device__ float g_Y2[(size_t)65536 * 128];        // hu per child (level-local rows)

struct Seg { const int* feats; int gp0, gq0, M, ctaEnd; };

__device__ __forceinline__ float sigf(float x) { return 1.0f / (1.0f + expf(-x)); }

// bf16 warp MMA (portable sm_80+): D[16x8] += A[16x16] * B[16x8]
__device__ __forceinline__ void mma16(float* c, const uint32_t* a, const uint32_t* b) {
    asm volatile(
        "mma.sync.aligned.m16n8k16.row.col.f32.bf16.bf16.f32 "
        "{%0,%1,%2,%3}, {%4,%5,%6,%7}, {%8,%9}, {%0,%1,%2,%3};"
        : "+f"(c[0]), "+f"(c[1]), "+f"(c[2]), "+f"(c[3])
        : "r"(a[0]), "r"(a[1]), "r"(a[2]), "r"(a[3]), "r"(b[0]), "r"(b[1]));
}

__device__ __forceinline__ void split2(float x, float y, uint32_t& hp, uint32_t& lp) {
    __nv_bfloat162 h = __floats2bfloat162_rn(x, y);
    hp = *(uint32_t*)&h;
    float lx = x - __bfloat162float(h.x);
    float ly = y - __bfloat162float(h.y);
    __nv_bfloat162 l = __floats2bfloat162_rn(lx, ly);
    lp = *(uint32_t*)&l;
}

// ---------------------------------------------------------------------------
// Prep kernels — ALL destination globals written BY NAME in device code.
// ---------------------------------------------------------------------------
__global__ void __launch_bounds__(256)
prepA_kernel(const float* __restrict__ emb)
{
    int idx = blockIdx.x * 256 + threadIdx.x;   // VT*128*64 total
    int v = idx >> 6, p = idx & 63;
    float x0 = 0.f, x1 = 0.f;
    if (v < VOCAB) {
        x0 = __ldg(&emb[(size_t)v * 128 + 2 * p]);
        x1 = __ldg(&emb[(size_t)v * 128 + 2 * p + 1]);
    }
    uint32_t hp, lp; split2(x0, x1, hp, lp);
    g_Ah[idx] = hp;
    g_Al[idx] = lp;
}

// [W_iou (k x 384) | W_f (k x 128)] -> transposed [n][kpair] hi/lo into g_Bh/g_Bl
__global__ void __launch_bounds__(256)
prepW_kernel(const float* __restrict__ M1, const float* __restrict__ M2)
{
    int idx = blockIdx.x * 256 + threadIdx.x;   // 512*64 total
    int n = idx >> 6, p = idx & 63;
    int k0 = 2 * p;
    float x0, x1;
    if (n < 384) {
        x0 = __ldg(&M1[(size_t)k0 * 384 + n]);
        x1 = __ldg(&M1[(size_t)(k0 + 1) * 384 + n]);
    } else {
        x0 = __ldg(&M2[(size_t)k0 * 128 + (n - 384)]);
        x1 = __ldg(&M2[(size_t)(k0 + 1) * 128 + (n - 384)]);
    }
    uint32_t hp, lp; split2(x0, x1, hp, lp);
    g_Bh[idx] = hp;
    g_Bl[idx] = lp;
}

// [U_iou (k x 384) | U_f (k x 128)] -> transposed [n][kpair] hi/lo into g_UH/g_UL
__global__ void __launch_bounds__(256)
prepU_kernel(const float* __restrict__ M1, const float* __restrict__ M2)
{
    int idx = blockIdx.x * 256 + threadIdx.x;   // 512*64 total
    int n = idx >> 6, p = idx & 63;
    int k0 = 2 * p;
    float x0, x1;
    if (n < 384) {
        x0 = __ldg(&M1[(size_t)k0 * 384 + n]);
        x1 = __ldg(&M1[(size_t)(k0 + 1) * 384 + n]);
    } else {
        x0 = __ldg(&M2[(size_t)k0 * 128 + (n - 384)]);
        x1 = __ldg(&M2[(size_t)(k0 + 1) * 128 + (n - 384)]);
    }
    uint32_t hp, lp; split2(x0, x1, hp, lp);
    g_UH[idx] = hp;
    g_UL[idx] = lp;
}

// ---------------------------------------------------------------------------
// Table GEMM (R12-proven, verbatim): T = emb @ [W_iou|W_f] + bias.
// ---------------------------------------------------------------------------
extern __shared__ uint32_t sh[];
__global__ void __launch_bounds__(256)
table_mma(const float* __restrict__ biou, const float* __restrict__ bf)
{
    const int tid = threadIdx.x, w = tid >> 5, lane = tid & 31;
    const int g = lane >> 2, tg = lane & 3;
    const int nBlk = blockIdx.y * 64;

    uint32_t* Ah = sh;                 // 128*68
    uint32_t* Al = sh + 8704;
    uint32_t* Bh = sh + 17408;         // 64*68
    uint32_t* Bl = sh + 21760;

    const uint4* srcAh = (const uint4*)(g_Ah + (size_t)blockIdx.x * 8192);
    const uint4* srcAl = (const uint4*)(g_Al + (size_t)blockIdx.x * 8192);
    for (int i = tid; i < 2048; i += 256) {
        int r = i >> 4, q = i & 15;
        *(uint4*)(Ah + r * 68 + q * 4) = srcAh[i];
        *(uint4*)(Al + r * 68 + q * 4) = srcAl[i];
    }
    for (int i = tid; i < 1024; i += 256) {
        int n = i >> 4, q = i & 15;
        *(uint4*)(Bh + n * 68 + q * 4) = *(const uint4*)(g_Bh + (size_t)(nBlk + n) * 64 + q * 4);
        *(uint4*)(Bl + n * 68 + q * 4) = *(const uint4*)(g_Bl + (size_t)(nBlk + n) * 64 + q * 4);
    }
    __syncthreads();

    const int wm = (w & 3) * 32;
    const int wn = (w >> 2) * 32;

    float acc[2][4][4];
    #pragma unroll
    for (int mt = 0; mt < 2; mt++)
        #pragma unroll
        for (int nt = 0; nt < 4; nt++)
            #pragma unroll
            for (int e = 0; e < 4; e++) acc[mt][nt][e] = 0.f;

    #pragma unroll
    for (int ks = 0; ks < 8; ks++) {
        const int p0 = ks * 8;
        uint32_t ah[2][4], al[2][4], bh[4][2], bl[4][2];
        #pragma unroll
        for (int mt = 0; mt < 2; mt++) {
            int r0 = wm + mt * 16 + g;
            ah[mt][0] = Ah[r0 * 68 + p0 + tg];
            ah[mt][1] = Ah[(r0 + 8) * 68 + p0 + tg];
            ah[mt][2] = Ah[r0 * 68 + p0 + tg + 4];
            ah[mt][3] = Ah[(r0 + 8) * 68 + p0 + tg + 4];
            al[mt][0] = Al[r0 * 68 + p0 + tg];
            al[mt][1] = Al[(r0 + 8) * 68 + p0 + tg];
            al[mt][2] = Al[r0 * 68 + p0 + tg + 4];
            al[mt][3] = Al[(r0 + 8) * 68 + p0 + tg + 4];
        }
        #pragma unroll
        for (int nt = 0; nt < 4; nt++) {
            int col = wn + nt * 8 + g;
            bh[nt][0] = Bh[col * 68 + p0 + tg];
            bh[nt][1] = Bh[col * 68 + p0 + tg + 4];
            bl[nt][0] = Bl[col * 68 + p0 + tg];
            bl[nt][1] = Bl[col * 68 + p0 + tg + 4];
        }
        #pragma unroll
        for (int mt = 0; mt < 2; mt++)
            #pragma unroll
            for (int nt = 0; nt < 4; nt++) {
                mma16(acc[mt][nt], ah[mt], bh[nt]);
                mma16(acc[mt][nt], al[mt], bh[nt]);
                mma16(acc[mt][nt], ah[mt], bl[nt]);
            }
    }

    #pragma unroll
    for (int mt = 0; mt < 2; mt++) {
        #pragma unroll
        for (int nt = 0; nt < 4; nt++) {
            int colg = nBlk + wn + nt * 8 + tg * 2;
            float bias0 = (colg < 384) ? __ldg(&biou[colg]) : __ldg(&bf[colg - 384]);
            float bias1 = (colg + 1 < 384) ? __ldg(&biou[colg + 1]) : __ldg(&bf[colg + 1 - 384]);
            int r0 = blockIdx.x * 128 + wm + mt * 16 + g;
            if (r0 < VOCAB) {
                g_T[(size_t)r0 * 512 + colg]     = acc[mt][nt][0] + bias0;
                g_T[(size_t)r0 * 512 + colg + 1] = acc[mt][nt][1] + bias1;
            }
            if (r0 + 8 < VOCAB) {
                g_T[(size_t)(r0 + 8) * 512 + colg]     = acc[mt][nt][2] + bias0;
                g_T[(size_t)(r0 + 8) * 512 + colg + 1] = acc[mt][nt][3] + bias1;
            }
        }
    }
}

// ---------------------------------------------------------------------------
// K1: Y1 = (h0+h1) @ U_iou  (M x 384). A built on the fly from g_h.
// grid = (M/128, 6). Mainloop is a LITERAL copy of table_mma's.
// ---------------------------------------------------------------------------
__global__ void __launch_bounds__(256)
mmaY1_kernel(int gq0)
{
    const int tid = threadIdx.x, w = tid >> 5, lane = tid & 31;
    const int g = lane >> 2, tg = lane & 3;
    const int nBlk = blockIdx.y * 64;    // < 384

    uint32_t* Ah = sh;
    uint32_t* Al = sh + 8704;
    uint32_t* Bh = sh + 17408;
    uint32_t* Bl = sh + 21760;

    const int rowBase = gq0 + blockIdx.x * 256;
    for (int i = tid; i < 8192; i += 256) {
        int r = i >> 6, p = i & 63;
        float2 a = ((const float2*)(g_h + (size_t)(rowBase + 2 * r) * 128))[p];
        float2 b = ((const float2*)(g_h + (size_t)(rowBase + 2 * r + 1) * 128))[p];
        uint32_t hp, lp; split2(a.x + b.x, a.y + b.y, hp, lp);
        Ah[r * 68 + p] = hp;
        Al[r * 68 + p] = lp;
    }
    for (int i = tid; i < 1024; i += 256) {
        int n = i >> 4, q = i & 15;
        *(uint4*)(Bh + n * 68 + q * 4) = *(const uint4*)(g_UH + (size_t)(nBlk + n) * 64 + q * 4);
        *(uint4*)(Bl + n * 68 + q * 4) = *(const uint4*)(g_UL + (size_t)(nBlk + n) * 64 + q * 4);
    }
    __syncthreads();

    const int wm = (w & 3) * 32;
    const int wn = (w >> 2) * 32;

    float acc[2][4][4];
    #pragma unroll
    for (int mt = 0; mt < 2; mt++)
        #pragma unroll
        for (int nt = 0; nt < 4; nt++)
            #pragma unroll
            for (int e = 0; e < 4; e++) acc[mt][nt][e] = 0.f;

    #pragma unroll
    for (int ks = 0; ks < 8; ks++) {
        const int p0 = ks * 8;
        uint32_t ah[2][4], al[2][4], bh[4][2], bl[4][2];
        #pragma unroll
        for (int mt = 0; mt < 2; mt++) {
            int r0 = wm + mt * 16 + g;
            ah[mt][0] = Ah[r0 * 68 + p0 + tg];
            ah[mt][1] = Ah[(r0 + 8) * 68 + p0 + tg];
            ah[mt][2] = Ah[r0 * 68 + p0 + tg + 4];
            ah[mt][3] = Ah[(r0 + 8) * 68 + p0 + tg + 4];
            al[mt][0] = Al[r0 * 68 + p0 + tg];
            al[mt][1] = Al[(r0 + 8) * 68 + p0 + tg];
            al[mt][2] = Al[r0 * 68 + p0 + tg + 4];
            al[mt][3] = Al[(r0 + 8) * 68 + p0 + tg + 4];
        }
        #pragma unroll
        for (int nt = 0; nt < 4; nt++) {
            int col = wn + nt * 8 + g;
            bh[nt][0] = Bh[col * 68 + p0 + tg];
            bh[nt][1] = Bh[col * 68 + p0 + tg + 4];
            bl[nt][0] = Bl[col * 68 + p0 + tg];
            bl[nt][1] = Bl[col * 68 + p0 + tg + 4];
        }
        #pragma unroll
        for (int mt = 0; mt < 2; mt++)
            #pragma unroll
            for (int nt = 0; nt < 4; nt++) {
                mma16(acc[mt][nt], ah[mt], bh[nt]);
                mma16(acc[mt][nt], al[mt], bh[nt]);
                mma16(acc[mt][nt], ah[mt], bl[nt]);
            }
    }

    #pragma unroll
    for (int mt = 0; mt < 2; mt++) {
        #pragma unroll
        for (int nt = 0; nt < 4; nt++) {
            int colg = nBlk + wn + nt * 8 + tg * 2;
            int r0 = blockIdx.x * 128 + wm + mt * 16 + g;
            g_Y1[(size_t)r0 * 384 + colg]           = acc[mt][nt][0];
            g_Y1[(size_t)r0 * 384 + colg + 1]       = acc[mt][nt][1];
            g_Y1[(size_t)(r0 + 8) * 384 + colg]     = acc[mt][nt][2];
            g_Y1[(size_t)(r0 + 8) * 384 + colg + 1] = acc[mt][nt][3];
        }
    }
}

// ---------------------------------------------------------------------------
// K2: Y2 = h_child @ U_f  (2M x 128). grid = (2M/128, 2).
// Mainloop: literal copy. Output indexed by LEVEL-LOCAL child row.
// ---------------------------------------------------------------------------
__global__ void __launch_bounds__(256)
mmaY2_kernel(int gq0)
{
    const int tid = threadIdx.x, w = tid >> 5, lane = tid & 31;
    const int g = lane >> 2, tg = lane & 3;
    const int nb = blockIdx.y;           // 0..1 -> U_f cols 0..63 / 64..127

    uint32_t* Ah = sh;
    uint32_t* Al = sh + 8704;
    uint32_t* Bh = sh + 17408;
    uint32_t* Bl = sh + 21760;

    const int rowBase = gq0 + blockIdx.x * 128;
    for (int i = tid; i < 8192; i += 256) {
        int r = i >> 6, p = i & 63;
        float2 a = ((const float2*)(g_h + (size_t)(rowBase + r) * 128))[p];
        uint32_t hp, lp; split2(a.x, a.y, hp, lp);
        Ah[r * 68 + p] = hp;
        Al[r * 68 + p] = lp;
    }
    const int bBase = 384 + nb * 64;
    for (int i = tid; i < 1024; i += 256) {
        int n = i >> 4, q = i & 15;
        *(uint4*)(Bh + n * 68 + q * 4) = *(const uint4*)(g_UH + (size_t)(bBase + n) * 64 + q * 4);
        *(uint4*)(Bl + n * 68 + q * 4) = *(const uint4*)(g_UL + (size_t)(bBase + n) * 64 + q * 4);
    }
    __syncthreads();

    const int wm = (w & 3) * 32;
    const int wn = (w >> 2) * 32;

    float acc[2][4][4];
    #pragma unroll
    for (int mt = 0; mt < 2; mt++)
        #pragma unroll
        for (int nt = 0; nt < 4; nt++)
            #pragma unroll
            for (int e = 0; e < 4; e++) acc[mt][nt][e] = 0.f;

    #pragma unroll
    for (int ks = 0; ks < 8; ks++) {
        const int p0 = ks * 8;
        uint32_t ah[2][4], al[2][4], bh[4][2], bl[4][2];
        #pragma unroll
        for (int mt = 0; mt < 2; mt++) {
            int r0 = wm + mt * 16 + g;
            ah[mt][0] = Ah[r0 * 68 + p0 + tg];
            ah[mt][1] = Ah[(r0 + 8) * 68 + p0 + tg];
            ah[mt][2] = Ah[r0 * 68 + p0 + tg + 4];
            ah[mt][3] = Ah[(r0 + 8) * 68 + p0 + tg + 4];
            al[mt][0] = Al[r0 * 68 + p0 + tg];
            al[mt][1] = Al[(r0 + 8) * 68 + p0 + tg];
            al[mt][2] = Al[r0 * 68 + p0 + tg + 4];
            al[mt][3] = Al[(r0 + 8) * 68 + p0 + tg + 4];
        }
        #pragma unroll
        for (int nt = 0; nt < 4; nt++) {
            int col = wn + nt * 8 + g;
            bh[nt][0] = Bh[col * 68 + p0 + tg];
            bh[nt][1] = Bh[col * 68 + p0 + tg + 4];
            bl[nt][0] = Bl[col * 68 + p0 + tg];
            bl[nt][1] = Bl[col * 68 + p0 + tg + 4];
        }
        #pragma unroll
        for (int mt = 0; mt < 2; mt++)
            #pragma unroll
            for (int nt = 0; nt < 4; nt++) {
                mma16(acc[mt][nt], ah[mt], bh[nt]);
                mma16(acc[mt][nt], al[mt], bh[nt]);
                mma16(acc[mt][nt], ah[mt], bl[nt]);
            }
    }

    #pragma unroll
    for (int mt = 0; mt < 2; mt++) {
        #pragma unroll
        for (int nt = 0; nt < 4; nt++) {
            int colg = nb * 64 + wn + nt * 8 + tg * 2;
            int r0 = blockIdx.x * 128 + wm + mt * 16 + g;   // level-local child row
            g_Y2[(size_t)r0 * 128 + colg]           = acc[mt][nt][0];
            g_Y2[(size_t)r0 * 128 + colg + 1]       = acc[mt][nt][1];
            g_Y2[(size_t)(r0 + 8) * 128 + colg]     = acc[mt][nt][2];
            g_Y2[(size_t)(r0 + 8) * 128 + colg + 1] = acc[mt][nt][3];
        }
    }
}

// ---------------------------------------------------------------------------
// Gate kernel: elementwise combine (leaf-shaped; low regs). grid = M/2.
// ---------------------------------------------------------------------------
__global__ void __launch_bounds__(256)
gate_kernel(const int* __restrict__ feats, int gp0, int gq0)
{
    int j = blockIdx.x * 2 + (threadIdx.x >> 7);   // level-local parent
    int col = threadIdx.x & 127;
    int gp = gp0 + j;
    int f = __ldg(&feats[j]);
    const float* Tf  = g_T + (size_t)f * 512;
    const float* Y1r = g_Y1 + (size_t)j * 384;
    float iv = sigf(__ldg(&Y1r[col])        + __ldg(&Tf[col]));
    float ov = sigf(__ldg(&Y1r[128 + col])  + __ldg(&Tf[128 + col]));
    float uv = tanhf(__ldg(&Y1r[256 + col]) + __ldg(&Tf[256 + col]));
    float xf = __ldg(&Tf[384 + col]);
    float f0 = sigf(xf + __ldg(&g_Y2[(size_t)(2 * j) * 128 + col]));
    float f1 = sigf(xf + __ldg(&g_Y2[(size_t)(2 * j + 1) * 128 + col]));
    float c0 = __ldg(&g_c[(size_t)(gq0 + 2 * j) * 128 + col]);
    float c1 = __ldg(&g_c[(size_t)(gq0 + 2 * j + 1) * 128 + col]);
    float cc = iv * uv + f0 * c0 + f1 * c1;
    g_c[(size_t)gp * 128 + col] = cc;
    g_h[(size_t)gp * 128 + col] = ov * tanhf(cc);
}

// ---------------------------------------------------------------------------
// Leaf kernel (proven, verbatim)
// ---------------------------------------------------------------------------
#define LEAVES_C 65536
#define LEAVES_AB 2048
__global__ void __launch_bounds__(256)
leaf_kernel(const int* __restrict__ cf, const int* __restrict__ af,
            const int* __restrict__ bfeat)
{
    int node = blockIdx.x * 2 + (threadIdx.x >> 7);
    int col = threadIdx.x & 127;
    int grow; const int* fp; int loc;
    if (node < LEAVES_C)                  { loc = node;                        grow = loc;           fp = cf; }
    else if (node < LEAVES_C + LEAVES_AB) { loc = node - LEAVES_C;             grow = NC + loc;      fp = af; }
    else                                  { loc = node - LEAVES_C - LEAVES_AB; grow = NC + NA + loc; fp = bfeat; }
    int f = __ldg(&fp[loc]);
    const float* T = g_T + (size_t)f * 512;
    float iv = sigf(__ldg(&T[col]));
    float ov = sigf(__ldg(&T[128 + col]));
    float uv = tanhf(__ldg(&T[256 + col]));
    float c = iv * uv;
    g_c[(size_t)grow * HDIM + col] = c;
    g_h[(size_t)grow * HDIM + col] = ov * tanhf(c);
}

// ---------------------------------------------------------------------------
// FFMA level kernel (R4/R12-proven, verbatim)
// ---------------------------------------------------------------------------
#define FMA4(acc, s, b) do { \
    (acc).x = fmaf((s), (b).x, (acc).x); (acc).y = fmaf((s), (b).y, (acc).y); \
    (acc).z = fmaf((s), (b).z, (acc).z); (acc).w = fmaf((s), (b).w, (acc).w); } while (0)

__global__ void __launch_bounds__(256)
level_kernel(Seg s0, Seg s1, Seg s2,
             const float* __restrict__ Uiou, const float* __restrict__ Uf)
{
    __shared__ float Hp[2 * TM * HDIM];
    __shared__ float Hs[TM * HDIM];

    int cta = blockIdx.x;
    Seg s; int rel;
    if (cta < s0.ctaEnd)      { s = s0; rel = cta; }
    else if (cta < s1.ctaEnd) { s = s1; rel = cta - s0.ctaEnd; }
    else                      { s = s2; rel = cta - s1.ctaEnd; }

    const int m0 = rel * TM;
    int Mrem = s.M - m0; if (Mrem > TM) Mrem = TM;
    const int tid = threadIdx.x;

    {
        const float4* gh4 = (const float4*)g_h;
        for (int i = tid; i < 2 * TM * 32; i += 256) {
            int r = i >> 5, q = i & 31;
            float4 v = make_float4(0.f, 0.f, 0.f, 0.f);
            if (r < 2 * Mrem)
                v = gh4[(size_t)(s.gq0 + 2 * m0 + r) * 32 + q];
            ((float4*)Hp)[i] = v;
        }
    }
    __syncthreads();
    for (int i = tid; i < TM * 32; i += 256) {
        int m = i >> 5, q = i & 31;
        float4 a = ((const float4*)Hp)[(2 * m) * 32 + q];
        float4 b = ((const float4*)Hp)[(2 * m + 1) * 32 + q];
        ((float4*)Hs)[i] = make_float4(a.x + b.x, a.y + b.y, a.z + b.z, a.w + b.w);
    }
    __syncthreads();

    const int ng = tid & 31;
    const int mb = (tid >> 5) * 4;

    float4 aI[4], aO[4], aU[4], aH0[4], aH1[4];
    #pragma unroll
    for (int mm = 0; mm < 4; mm++) {
        aI[mm] = make_float4(0,0,0,0); aO[mm] = aI[mm]; aU[mm] = aI[mm];
        aH0[mm] = aI[mm]; aH1[mm] = aI[mm];
    }

    const float4* U4  = (const float4*)Uiou;
    const float4* Uf4 = (const float4*)Uf;

    float4 ui = __ldg(&U4[ng]);
    float4 uo = __ldg(&U4[ng + 32]);
    float4 uu = __ldg(&U4[ng + 64]);
    float4 uf = __ldg(&Uf4[ng]);

    #pragma unroll 2
    for (int k = 0; k < 127; k++) {
        const int r = (k + 1) * 96 + ng;
        float4 nui = __ldg(&U4[r]);
        float4 nuo = __ldg(&U4[r + 32]);
        float4 nuu = __ldg(&U4[r + 64]);
        float4 nuf = __ldg(&Uf4[(k + 1) * 32 + ng]);
        #pragma unroll
        for (int mm = 0; mm < 4; mm++) {
            float hs = Hs[(mb + mm) * HDIM + k];
            float h0 = Hp[(2 * (mb + mm)) * HDIM + k];
            float h1 = Hp[(2 * (mb + mm) + 1) * HDIM + k];
            FMA4(aI[mm], hs, ui); FMA4(aO[mm], hs, uo); FMA4(aU[mm], hs, uu);
            FMA4(aH0[mm], h0, uf); FMA4(aH1[mm], h1, uf);
        }
        ui = nui; uo = nuo; uu = nuu; uf = nuf;
    }
    {
        const int k = 127;
        #pragma unroll
        for (int mm = 0; mm < 4; mm++) {
            float hs = Hs[(mb + mm) * HDIM + k];
            float h0 = Hp[(2 * (mb + mm)) * HDIM + k];
            float h1 = Hp[(2 * (mb + mm) + 1) * HDIM + k];
            FMA4(aI[mm], hs, ui); FMA4(aO[mm], hs, uo); FMA4(aU[mm], hs, uu);
            FMA4(aH0[mm], h0, uf); FMA4(aH1[mm], h1, uf);
        }
    }

    #pragma unroll
    for (int mm = 0; mm < 4; mm++) {
        int mi = mb + mm;
        if (mi >= Mrem) continue;
        int gp = s.gp0 + m0 + mi;
        int f = __ldg(&s.feats[m0 + mi]);

        const float4* T4 = (const float4*)(g_T + (size_t)f * 512);
        float4 ti  = __ldg(&T4[ng]);
        float4 to  = __ldg(&T4[32 + ng]);
        float4 tu  = __ldg(&T4[64 + ng]);
        float4 txf = __ldg(&T4[96 + ng]);

        size_t cb = (size_t)(s.gq0 + 2 * (m0 + mi)) * 32 + ng;
        float4 c0v = ((const float4*)g_c)[cb];
        float4 c1v = ((const float4*)g_c)[cb + 32];

        const float *pI = (const float*)&aI[mm], *pO = (const float*)&aO[mm];
        const float *pU = (const float*)&aU[mm];
        const float *pH0 = (const float*)&aH0[mm], *pH1 = (const float*)&aH1[mm];
        const float *pti = (const float*)&ti, *pto = (const float*)&to;
        const float *ptu = (const float*)&tu, *pxf = (const float*)&txf;
        const float *pc0 = (const float*)&c0v, *pc1 = (const float*)&c1v;

        float4 cn, hn;
        float* pcn = (float*)&cn; float* phn = (float*)&hn;
        #pragma unroll
        for (int nn = 0; nn < 4; nn++) {
            float iv = sigf(pI[nn] + pti[nn]);
            float ov = sigf(pO[nn] + pto[nn]);
            float uv = tanhf(pU[nn] + ptu[nn]);
            float f0 = sigf(pxf[nn] + pH0[nn]);
            float f1 = sigf(pxf[nn] + pH1[nn]);
            float cv = iv * uv + f0 * pc0[nn] + f1 * pc1[nn];
            pcn[nn] = cv;
            phn[nn] = ov * tanhf(cv);
        }
        ((float4*)g_c)[(size_t)gp * 32 + ng] = cn;
        ((float4*)g_h)[(size_t)gp * 32 + ng] = hn;
    }
}

// ---------------------------------------------------------------------------
// Fusion head
// ---------------------------------------------------------------------------
__global__ void final_kernel(const float* __restrict__ fc1w, const float* __restrict__ fc1b,
                             const float* __restrict__ fc2w, const float* __restrict__ fc2b,
                             float* __restrict__ out)
{
    __shared__ float red[128]; __shared__ float hv[128]; __shared__ float y1[64];
    int t = threadIdx.x;
    const float* hC = g_h + (size_t)(NC - 1) * HDIM;
    const float* hA = g_h + (size_t)(NC + NA - 1) * HDIM;
    const float* hB = g_h + (size_t)(NC + NA + NB - 1) * HDIM;
    red[t] = hB[t] * hC[t];
    __syncthreads();
    for (int ss = 64; ss > 0; ss >>= 1) { if (t < ss) red[t] += red[t + ss]; __syncthreads(); }
    hv[t] = hA[t] * red[0];
    __syncthreads();
    if (t < 64) {
        float a = fc1b[t];
        #pragma unroll 4
        for (int i = 0; i < 128; i++) a = fmaf(hv[i], fc1w[i * 64 + t], a);
        y1[t] = fmaxf(a, 0.f);
    }
    __syncthreads();
    if (t < 3) {
        float a = fc2b[t];
        #pragma unroll
        for (int i = 0; i < 64; i++) a = fmaf(y1[i], fc2w[i * 3 + t], a);
        out[t] = fmaxf(a, 0.f);
    }
}

// ---------------------------------------------------------------------------
// Host side
// ---------------------------------------------------------------------------
static inline Seg make_seg(const int* feats, int base, int D, int it)
{
    int N = (1 << D) - 1;
    int d = D - 1 - it;
    Seg s;
    s.M = 1 << d;
    int pLoc = N - (1 << (d + 1)) + 1;
    int qLoc = N - (1 << (d + 2)) + 1;
    s.feats = feats + pLoc; s.gp0 = base + pLoc; s.gq0 = base + qLoc; s.ctaEnd = 0;
    return s;
}
static inline Seg empty_seg() { Seg s{nullptr, 0, 0, 0, 0}; return s; }

extern "C" void kernel_launch(void* const* d_in, const int* in_sizes, int n_in,
                              void* d_out, int out_size)
{
    const int*   cf    = (const int*)  d_in[0];
    const int*   af    = (const int*)  d_in[4];
    const int*   bfeat = (const int*)  d_in[8];
    const float* emb   = (const float*)d_in[12];
    const float* W_iou = (const float*)d_in[13];
    const float* b_iou = (const float*)d_in[14];
    const float* U_iou = (const float*)d_in[15];
    const float* W_f   = (const float*)d_in[16];
    const float* b_f   = (const float*)d_in[17];
    const float* U_f   = (const float*)d_in[18];
    const float* fc1w  = (const float*)d_in[19];
    const float* fc1b  = (const float*)d_in[20];
    const float* fc2w  = (const float*)d_in[21];
    const float* fc2b  = (const float*)d_in[22];

    const int SM_AB = 104448;   // A/B split tiles (26112 u32)
    cudaFuncSetAttribute(table_mma,    cudaFuncAttributeMaxDynamicSharedMemorySize, SM_AB);
    cudaFuncSetAttribute(mmaY1_kernel, cudaFuncAttributeMaxDynamicSharedMemorySize, SM_AB);
    cudaFuncSetAttribute(mmaY2_kernel, cudaFuncAttributeMaxDynamicSharedMemorySize, SM_AB);

    prepA_kernel<<<VT * 32, 256>>>(emb);
    prepW_kernel<<<128, 256>>>(W_iou, W_f);
    prepU_kernel<<<128, 256>>>(U_iou, U_f);
    {
        dim3 grid(VT, 8);
        table_mma<<<grid, 256, SM_AB>>>(b_iou, b_f);
    }
    leaf_kernel<<<(LEAVES_C + 2 * LEAVES_AB) / 2, 256>>>(cf, af, bfeat);

    const int baseC = 0, baseA = NC, baseB = NC + NA;
    for (int it = 1; it < 17; it++) {
        if (it <= 5) {
            // big cube level on tensor cores (M = 32768 >> (it-1))
            Seg sc = make_seg(cf, baseC, 17, it);
            { dim3 g1(sc.M / 128, 6);     mmaY1_kernel<<<g1, 256, SM_AB>>>(sc.gq0); }
            { dim3 g2(2 * sc.M / 128, 2); mmaY2_kernel<<<g2, 256, SM_AB>>>(sc.gq0); }
            gate_kernel<<<sc.M / 2, 256>>>(sc.feats, sc.gp0, sc.gq0);
            // a/b trees on FFMA path
            Seg s0 = empty_seg();
            Seg s1 = make_seg(af, baseA, 12, it);
            Seg s2 = make_seg(bfeat, baseB, 12, it);
            int e1 = (s1.M + TM - 1) / TM;
            int e2 = e1 + (s2.M + TM - 1) / TM;
            s0.ctaEnd = 0; s1.ctaEnd = e1; s2.ctaEnd = e2;
            level_kernel<<<e2, 256>>>(s0, s1, s2, U_iou, U_f);
        } else {
            Seg s0 = make_seg(cf, baseC, 17, it);
            Seg s1 = (it <= 11) ? make_seg(af, baseA, 12, it) : empty_seg();
            Seg s2 = (it <= 11) ? make_seg(bfeat, baseB, 12, it) : empty_seg();
            int e0 = (s0.M + TM - 1) / TM;
            int e1 = e0 + (s1.M > 0 ? (s1.M + TM - 1) / TM : 0);
            int e2 = e1 + (s2.M > 0 ? (s2.M + TM - 1) / TM : 0);
            s0.ctaEnd = e0; s1.ctaEnd = e1; s2.ctaEnd = e2;
            level_kernel<<<e2, 256>>>(s0, s1, s2, U_iou, U_f);
        }
    }

    final_kernel<<<1, 128>>>(fc1w, fc1b, fc2w, fc2b, (float*)d_out);
}